// round 15
// baseline (speedup 1.0000x reference)
#include <cuda_runtime.h>
#include <cuda_fp16.h>
#include <cstdint>

#define BSZ  2
#define SEQ  2048
#define EMB  1024
#define NH   16
#define HD   64
#define NROWS (BSZ*NH*SEQ)
#define NTOK  (BSZ*SEQ)
#define SW   72
#define SWW  36
#define QSCALE 0.045084220027780106f   // (1/32) * log2(e)
#define HONES 0x3C003C00u              // half2(1.0, 1.0)

__device__ __half g_Qp[NROWS*HD];      // [head][s][d] fp16, pre-scaled
__device__ __half g_Kp[NROWS*HD];      // [head][s][d] fp16
__device__ __half g_Vt[NROWS*HD];      // [head][d][s] fp16 (transposed)
__device__ __half g_O [NROWS*HD];      // flat == [NTOK][EMB] fp16
__device__ __half g_Wt[EMB*EMB];       // Wo fp16
__device__ uint32_t g_mbits[BSZ*SEQ*(SEQ/32)];   // 1 MB bitmask

// ---------------------------------------------------------------------------
// NOTE: mma16 is intentionally NOT volatile — it is register-pure, and
// letting the compiler reorder it against later ldmatrix ops is what enables
// smem/tensor overlap.
__device__ __forceinline__ void mma16(float c[4],
    uint32_t a0, uint32_t a1, uint32_t a2, uint32_t a3, uint32_t b0, uint32_t b1)
{
    asm(
      "mma.sync.aligned.m16n8k16.row.col.f32.f16.f16.f32 "
      "{%0,%1,%2,%3}, {%4,%5,%6,%7}, {%8,%9}, {%0,%1,%2,%3};"
      : "+f"(c[0]), "+f"(c[1]), "+f"(c[2]), "+f"(c[3])
      : "r"(a0), "r"(a1), "r"(a2), "r"(a3), "r"(b0), "r"(b1));
}
__device__ __forceinline__ void ldsm4(uint32_t& r0, uint32_t& r1,
                                      uint32_t& r2, uint32_t& r3, uint32_t a)
{
    asm volatile("ldmatrix.sync.aligned.m8n8.x4.shared.b16 {%0,%1,%2,%3}, [%4];"
                 : "=r"(r0), "=r"(r1), "=r"(r2), "=r"(r3) : "r"(a));
}
__device__ __forceinline__ uint32_t packh2(float a, float b) {
    __half2 h = __floats2half2_rn(a, b);
    return *(uint32_t*)&h;
}
__device__ __forceinline__ uint32_t ex2h2(uint32_t x) {
    uint32_t r; asm("ex2.approx.f16x2 %0, %1;" : "=r"(r) : "r"(x)); return r;
}
__device__ __forceinline__ float msel(float s, uint32_t mw, uint32_t bit) {
    return (mw & bit) ? s : -30.f;
}
__device__ __forceinline__ void cpa16(void* s, const void* g) {
    uint32_t sa = (uint32_t)__cvta_generic_to_shared(s);
    asm volatile("cp.async.cg.shared.global [%0], [%1], 16;" :: "r"(sa), "l"(g));
}
#define CP_COMMIT()  asm volatile("cp.async.commit_group;")
#define CP_WAIT1()   asm volatile("cp.async.wait_group 1;")
#define CP_WAIT0()   asm volatile("cp.async.wait_group 0;")

// ---------------------------------------------------------------------------
// prep: mask bit-pack + Wo fp16 round in ONE launch
// ---------------------------------------------------------------------------
__global__ __launch_bounds__(256) void prep(const int* __restrict__ mask,
                                            const float* __restrict__ Wo)
{
    if (blockIdx.x < 32768) {
        int idx = blockIdx.x * 256 + threadIdx.x;
        uint32_t w = __ballot_sync(0xffffffffu, mask[idx] != 0);
        if ((threadIdx.x & 31) == 0) g_mbits[idx >> 5] = w;
    } else {
        int i = (blockIdx.x - 32768) * 256 + threadIdx.x;
        g_Wt[i] = __float2half_rn(Wo[i]);
    }
}

// ---------------------------------------------------------------------------
// Stage 1: projections v2 (unchanged from R13/R14, known good)
// ---------------------------------------------------------------------------
__global__ __launch_bounds__(256) void proj_mma(
    const float* __restrict__ Xq, const float* __restrict__ Xk, const float* __restrict__ Xv,
    const float* __restrict__ Wq, const float* __restrict__ Wk, const float* __restrict__ Wv)
{
    const float* X; const float* W;
    if (blockIdx.y == 0)      { X = Xq; W = Wq; }
    else if (blockIdx.y == 1) { X = Xk; W = Wk; }
    else                      { X = Xv; W = Wv; }

    __shared__ __half Xs[128*SW];
    __shared__ __half Ws[64*SW];
    const int tid = threadIdx.x, lane = tid & 31, w = tid >> 5;
    const size_t rb = (size_t)blockIdx.x * 128;

    float4 xv[8];
    const float4* Xg = (const float4*)(X + rb * 64);
    #pragma unroll
    for (int i = 0; i < 8; i++) xv[i] = Xg[tid + 256*i];
    float4 wv[4];
    const float4* Wg = (const float4*)W;
    #pragma unroll
    for (int i = 0; i < 4; i++) wv[i] = Wg[tid + 256*i];

    #pragma unroll
    for (int i = 0; i < 8; i++) {
        int v = tid + 256*i;
        int r = v >> 4, c4 = v & 15;
        uint32_t* dst = (uint32_t*)Xs + r*SWW + c4*2;
        dst[0] = packh2(xv[i].x, xv[i].y);
        dst[1] = packh2(xv[i].z, xv[i].w);
    }
    #pragma unroll
    for (int i = 0; i < 4; i++) {
        int v = tid + 256*i;
        int r = v >> 4, c4 = v & 15;
        uint32_t* dst = (uint32_t*)Ws + r*SWW + c4*2;
        dst[0] = packh2(wv[i].x, wv[i].y);
        dst[1] = packh2(wv[i].z, wv[i].w);
    }
    __syncthreads();

    const int g = lane >> 2, t = lane & 3;
    const uint32_t lofs = ((lane & 7) + ((lane >> 3) & 1) * 8) * (SW*2) + (lane >> 4) * 16;
    const uint32_t xb = (uint32_t)__cvta_generic_to_shared(Xs) + (16*w)*(SW*2) + lofs;
    const uint32_t wb = (uint32_t)__cvta_generic_to_shared(Ws) + lofs;

    float acc[8][4] = {};
    #pragma unroll
    for (int kc = 0; kc < 4; kc++) {
        uint32_t a0,a1,a2,a3;
        ldsm4(a0,a1,a2,a3, xb + kc*32);
        #pragma unroll
        for (int np = 0; np < 4; np++) {
            uint32_t b0,b1,b2,b3;
            ldsm4(b0,b1,b2,b3, wb + np*16*(SW*2) + kc*32);
            mma16(acc[2*np  ], a0,a1,a2,a3, b0, b2);
            mma16(acc[2*np+1], a0,a1,a2,a3, b1, b3);
        }
    }

    if (blockIdx.y == 0) {
        #pragma unroll
        for (int nt = 0; nt < 8; nt++)
            #pragma unroll
            for (int e = 0; e < 4; e++) acc[nt][e] *= QSCALE;
    }

    if (blockIdx.y < 2) {
        uint32_t* Yw = (uint32_t*)((blockIdx.y == 0) ? g_Qp : g_Kp);
        const size_t rr = rb + 16*w + g;
        #pragma unroll
        for (int nt = 0; nt < 8; nt++) {
            Yw[(rr   ) * 32 + 4*nt + t] = packh2(acc[nt][0], acc[nt][1]);
            Yw[(rr+8 ) * 32 + 4*nt + t] = packh2(acc[nt][2], acc[nt][3]);
        }
    } else {
        const int head = (int)(rb >> 11);
        const int s0 = (int)(rb & 2047) + 16*w + g;
        __half* Vb = g_Vt + (size_t)head * (64*2048);
        #pragma unroll
        for (int nt = 0; nt < 8; nt++) {
            int d0 = 8*nt + 2*t;
            Vb[(size_t)(d0  )*2048 + s0    ] = __float2half_rn(acc[nt][0]);
            Vb[(size_t)(d0+1)*2048 + s0    ] = __float2half_rn(acc[nt][1]);
            Vb[(size_t)(d0  )*2048 + s0 + 8] = __float2half_rn(acc[nt][2]);
            Vb[(size_t)(d0+1)*2048 + s0 + 8] = __float2half_rn(acc[nt][3]);
        }
    }
}

// ---------------------------------------------------------------------------
// Stage 2: fp16 flash attention — R5 math + Q persistent in registers +
// non-volatile mma (compiler can interleave HMMA with next LDSMs).
// ---------------------------------------------------------------------------
__global__ __launch_bounds__(128) void attn_mma()
{
    extern __shared__ __half sm[];
    __half* Qs   = sm;                        // 128*SW
    __half* Kbuf = sm + 128*SW;               // 2 x 64*SW
    __half* Vbuf = sm + 128*SW + 2*64*SW;     // 2 x 64*SW (Vt layout [d][s])

    const int tid = threadIdx.x, lane = tid & 31, w = tid >> 5;
    const int qb = blockIdx.x * 128, h = blockIdx.y, b = blockIdx.z;
    const int head = b * NH + h;
    const __half* Qp = g_Qp + (size_t)head * SEQ * HD + (size_t)qb * HD;
    const __half* Kp = g_Kp + (size_t)head * SEQ * HD;
    const __half* Vp = g_Vt + (size_t)head * (64*2048);

    // group 0: Q
    for (int v = tid; v < 1024; v += 128) {
        int r = v >> 3, c = (v & 7) * 8;
        cpa16(Qs + r*SW + c, Qp + (size_t)r*64 + c);
    }
    CP_COMMIT();
    // group 1: K0/V0
    for (int v = tid; v < 512; v += 128) {
        int r = v >> 3, c = (v & 7) * 8;
        cpa16(Kbuf + r*SW + c, Kp + (size_t)r*64 + c);
        cpa16(Vbuf + r*SW + c, Vp + (size_t)r*2048 + c);
    }
    CP_COMMIT();

    const int g = lane >> 2, t = lane & 3;
    const int r0 = 32*w + g;
    const uint32_t* mrow[4];
    #pragma unroll
    for (int i = 0; i < 4; i++)
        mrow[i] = g_mbits + ((size_t)b * SEQ + qb + r0 + 8*i) * (SEQ/32);

    const uint32_t lofs = ((lane & 7) + ((lane >> 3) & 1) * 8) * (SW*2) + (lane >> 4) * 16;
    const uint32_t qb0 = (uint32_t)__cvta_generic_to_shared(Qs) + (32*w)*(SW*2) + lofs;
    const uint32_t kb0 = (uint32_t)__cvta_generic_to_shared(Kbuf) + lofs;
    const uint32_t vb0 = (uint32_t)__cvta_generic_to_shared(Vbuf) + lofs;
    const uint32_t bufB = 64*SW*2;

    // wait for Q (group1 may still be in flight), load Q fragments once
    CP_WAIT1();
    __syncthreads();
    uint32_t qf[4][8];
    #pragma unroll
    for (int kc = 0; kc < 4; kc++) {
        ldsm4(qf[kc][0], qf[kc][1], qf[kc][2], qf[kc][3], qb0 + kc*32);
        ldsm4(qf[kc][4], qf[kc][5], qf[kc][6], qf[kc][7], qb0 + 16*(SW*2) + kc*32);
    }

    float o0[8][4] = {}, o1[8][4] = {};
    float lac0[4] = {}, lac1[4] = {};

    for (int it = 0; it < 32; ++it) {
        if (it + 1 < 32) {
            const __half* Kn = Kp + (size_t)(it+1) * 64 * 64;
            const __half* Vn = Vp + (size_t)(it+1) * 64;
            __half* kd = Kbuf + ((it+1)&1) * 64*SW;
            __half* vd = Vbuf + ((it+1)&1) * 64*SW;
            for (int v = tid; v < 512; v += 128) {
                int r = v >> 3, c = (v & 7) * 8;
                cpa16(kd + r*SW + c, Kn + (size_t)r*64 + c);
                cpa16(vd + r*SW + c, Vn + (size_t)r*2048 + c);
            }
            CP_COMMIT();
            CP_WAIT1();
        } else {
            CP_WAIT0();
        }
        __syncthreads();
        const uint32_t kcur = kb0 + (it&1) * bufB;
        const uint32_t vcur = vb0 + (it&1) * bufB;

        // S = Q @ K^T  (fp32 accum; Q pre-scaled so S is the exp2 argument)
        float s0[8][4] = {}, s1[8][4] = {};
        #pragma unroll
        for (int kc = 0; kc < 4; kc++) {
            #pragma unroll
            for (int np = 0; np < 4; np++) {
                uint32_t kb0r,kb1r,kb2r,kb3r;
                ldsm4(kb0r,kb1r,kb2r,kb3r, kcur + np*16*(SW*2) + kc*32);
                mma16(s0[2*np  ], qf[kc][0],qf[kc][1],qf[kc][2],qf[kc][3], kb0r, kb2r);
                mma16(s0[2*np+1], qf[kc][0],qf[kc][1],qf[kc][2],qf[kc][3], kb1r, kb3r);
                mma16(s1[2*np  ], qf[kc][4],qf[kc][5],qf[kc][6],qf[kc][7], kb0r, kb2r);
                mma16(s1[2*np+1], qf[kc][4],qf[kc][5],qf[kc][6],qf[kc][7], kb1r, kb3r);
            }
        }

        const int wi = it * 2;
        uint32_t mwa[4], mwb[4];
        #pragma unroll
        for (int i = 0; i < 4; i++) { mwa[i] = mrow[i][wi]; mwb[i] = mrow[i][wi+1]; }

        #pragma unroll
        for (int sc = 0; sc < 4; sc++) {
            const uint32_t m0 = (sc < 2) ? mwa[0] : mwb[0];
            const uint32_t m1 = (sc < 2) ? mwa[1] : mwb[1];
            const uint32_t m2 = (sc < 2) ? mwa[2] : mwb[2];
            const uint32_t m3 = (sc < 2) ? mwa[3] : mwb[3];
            const uint32_t cb = (uint32_t)(16*sc + 2*t) & 31u;
            const uint32_t bb0 = 1u << cb, bb1 = bb0 << 1, bb2 = bb0 << 8, bb3 = bb0 << 9;

            uint32_t a0 = ex2h2(packh2(msel(s0[2*sc  ][0],m0,bb0), msel(s0[2*sc  ][1],m0,bb1)));
            uint32_t a1 = ex2h2(packh2(msel(s0[2*sc  ][2],m1,bb0), msel(s0[2*sc  ][3],m1,bb1)));
            uint32_t a2 = ex2h2(packh2(msel(s0[2*sc+1][0],m0,bb2), msel(s0[2*sc+1][1],m0,bb3)));
            uint32_t a3 = ex2h2(packh2(msel(s0[2*sc+1][2],m1,bb2), msel(s0[2*sc+1][3],m1,bb3)));
            uint32_t a4 = ex2h2(packh2(msel(s1[2*sc  ][0],m2,bb0), msel(s1[2*sc  ][1],m2,bb1)));
            uint32_t a5 = ex2h2(packh2(msel(s1[2*sc  ][2],m3,bb0), msel(s1[2*sc  ][3],m3,bb1)));
            uint32_t a6 = ex2h2(packh2(msel(s1[2*sc+1][0],m2,bb2), msel(s1[2*sc+1][1],m2,bb3)));
            uint32_t a7 = ex2h2(packh2(msel(s1[2*sc+1][2],m3,bb2), msel(s1[2*sc+1][3],m3,bb3)));

            mma16(lac0, a0,a1,a2,a3, HONES, HONES);
            mma16(lac1, a4,a5,a6,a7, HONES, HONES);

            #pragma unroll
            for (int dp = 0; dp < 4; dp++) {
                uint32_t vb0r,vb1r,vb2r,vb3r;
                ldsm4(vb0r,vb1r,vb2r,vb3r, vcur + dp*16*(SW*2) + sc*32);
                mma16(o0[2*dp  ], a0,a1,a2,a3, vb0r, vb2r);
                mma16(o0[2*dp+1], a0,a1,a2,a3, vb1r, vb3r);
                mma16(o1[2*dp  ], a4,a5,a6,a7, vb0r, vb2r);
                mma16(o1[2*dp+1], a4,a5,a6,a7, vb1r, vb3r);
            }
        }
        __syncthreads();
    }

    const float il0 = 1.f / lac0[0], il1 = 1.f / lac0[2];
    const float il2 = 1.f / lac1[0], il3 = 1.f / lac1[2];

    uint32_t* Ow = (uint32_t*)(g_O + (size_t)head * SEQ * HD + (size_t)(qb + r0) * 64);
    #pragma unroll
    for (int dt = 0; dt < 8; dt++) {
        int cw = 4*dt + t;
        Ow[          cw] = packh2(o0[dt][0]*il0, o0[dt][1]*il0);
        Ow[ 8*32   + cw] = packh2(o0[dt][2]*il1, o0[dt][3]*il1);
        Ow[16*32   + cw] = packh2(o1[dt][0]*il2, o1[dt][1]*il2);
        Ow[24*32   + cw] = packh2(o1[dt][2]*il3, o1[dt][3]*il3);
    }
}

// ---------------------------------------------------------------------------
// Stage 3: output projection — 256 threads / 8 warps (4m x 2n), CTA tile
// M128 x N128, warp M32 x N64. Single full wave (256 CTAs, 2/SM).
// ---------------------------------------------------------------------------
__global__ __launch_bounds__(256) void outproj_mma(
    const float* __restrict__ bo, float* __restrict__ out)
{
    extern __shared__ __half sm[];
    __half* Abuf = sm;                  // 2 x 128*SW
    __half* Bbuf = sm + 2*128*SW;       // 2 x 128*SW

    const int tid = threadIdx.x, lane = tid & 31, w = tid >> 5;
    const int g = lane >> 2, t = lane & 3;
    const int wr = w >> 1, wc = w & 1;          // 4x2 warp grid
    const int nb = blockIdx.x * 128, eb = blockIdx.y * 128;

    for (int v = tid; v < 1024; v += 256) {
        int r = v >> 3, c = (v & 7) * 8;
        cpa16(Abuf + r*SW + c, g_O  + (size_t)(nb + r) * EMB + c);
        cpa16(Bbuf + r*SW + c, g_Wt + (size_t)(eb + r) * EMB + c);
    }
    CP_COMMIT();

    const uint32_t lofs = ((lane & 7) + ((lane >> 3) & 1) * 8) * (SW*2) + (lane >> 4) * 16;
    const uint32_t ab0 = (uint32_t)__cvta_generic_to_shared(Abuf) + (32*wr)*(SW*2) + lofs;
    const uint32_t bb0 = (uint32_t)__cvta_generic_to_shared(Bbuf) + (64*wc)*(SW*2) + lofs;
    const uint32_t bufB = 128*SW*2;

    float acc[2][8][4] = {};

    for (int it = 0; it < 16; ++it) {
        if (it + 1 < 16) {
            const int cb = (it + 1) * 64;
            __half* ad = Abuf + ((it+1)&1) * 128*SW;
            __half* bd = Bbuf + ((it+1)&1) * 128*SW;
            for (int v = tid; v < 1024; v += 256) {
                int r = v >> 3, c = (v & 7) * 8;
                cpa16(ad + r*SW + c, g_O  + (size_t)(nb + r) * EMB + cb + c);
                cpa16(bd + r*SW + c, g_Wt + (size_t)(eb + r) * EMB + cb + c);
            }
            CP_COMMIT();
            CP_WAIT1();
        } else {
            CP_WAIT0();
        }
        __syncthreads();
        const uint32_t acur = ab0 + (it&1) * bufB;
        const uint32_t bcur = bb0 + (it&1) * bufB;

        #pragma unroll
        for (int kc = 0; kc < 4; kc++) {
            uint32_t af[2][4];
            #pragma unroll
            for (int m = 0; m < 2; m++)
                ldsm4(af[m][0], af[m][1], af[m][2], af[m][3],
                      acur + m*16*(SW*2) + kc*32);
            #pragma unroll
            for (int np = 0; np < 4; np++) {
                uint32_t b0r,b1r,b2r,b3r;
                ldsm4(b0r,b1r,b2r,b3r, bcur + np*16*(SW*2) + kc*32);
                #pragma unroll
                for (int m = 0; m < 2; m++) {
                    mma16(acc[m][2*np  ], af[m][0],af[m][1],af[m][2],af[m][3], b0r, b2r);
                    mma16(acc[m][2*np+1], af[m][0],af[m][1],af[m][2],af[m][3], b1r, b3r);
                }
            }
        }
        __syncthreads();
    }

    #pragma unroll
    for (int m = 0; m < 2; m++) {
        const int row0 = nb + 32*wr + 16*m + g;
        #pragma unroll
        for (int nt = 0; nt < 8; nt++) {
            int c0 = eb + 64*wc + 8*nt + 2*t;
            float b0 = bo[c0], b1 = bo[c0+1];
            *(float2*)(out + (size_t)row0     * EMB + c0) =
                make_float2(acc[m][nt][0] + b0, acc[m][nt][1] + b1);
            *(float2*)(out + (size_t)(row0+8) * EMB + c0) =
                make_float2(acc[m][nt][2] + b0, acc[m][nt][3] + b1);
        }
    }
}

// ---------------------------------------------------------------------------
extern "C" void kernel_launch(void* const* d_in, const int* in_sizes, int n_in,
                              void* d_out, int out_size)
{
    const float* query = (const float*)d_in[0];
    const float* key   = (const float*)d_in[1];
    const float* value = (const float*)d_in[2];
    const int*   mask  = (const int*)  d_in[3];
    const float* Wq    = (const float*)d_in[4];
    const float* Wk    = (const float*)d_in[5];
    const float* Wv    = (const float*)d_in[6];
    const float* Wo    = (const float*)d_in[7];
    const float* bo    = (const float*)d_in[8];
    float* out = (float*)d_out;

    prep<<<32768 + 4096, 256>>>(mask, Wo);

    dim3 pg(NROWS/128, 3, 1);
    proj_mma<<<pg, 256>>>(query, key, value, Wq, Wk, Wv);

    const int attn_smem = (128*SW + 4*64*SW) * 2;   // 55,296 B
    cudaFuncSetAttribute(attn_mma, cudaFuncAttributeMaxDynamicSharedMemorySize, attn_smem);
    dim3 ag(SEQ/128, NH, BSZ);
    attn_mma<<<ag, 128, attn_smem>>>();

    const int op_smem = 4*128*SW*2;                 // 73,728 B
    cudaFuncSetAttribute(outproj_mma, cudaFuncAttributeMaxDynamicSharedMemorySize, op_smem);
    dim3 og(NTOK/128, EMB/128, 1);
    outproj_mma<<<og, 256, op_smem>>>(bo, out);
}

// round 16
// speedup vs baseline: 1.0119x; 1.0119x over previous
#include <cuda_runtime.h>
#include <cuda_fp16.h>
#include <cstdint>

#define BSZ  2
#define SEQ  2048
#define EMB  1024
#define NH   16
#define HD   64
#define NROWS (BSZ*NH*SEQ)
#define NTOK  (BSZ*SEQ)
#define SW   72
#define SWW  36
#define QSCALE 0.045084220027780106f   // (1/32) * log2(e)
#define HONES 0x3C003C00u              // half2(1.0, 1.0)

__device__ __half g_Qp[NROWS*HD];      // [head][s][d] fp16, pre-scaled
__device__ __half g_Kp[NROWS*HD];      // [head][s][d] fp16
__device__ __half g_Vt[NROWS*HD];      // [head][d][s] fp16 (transposed)
__device__ __half g_O [NROWS*HD];      // flat == [NTOK][EMB] fp16
__device__ __half g_Wt[EMB*EMB];       // Wo fp16
__device__ uint32_t g_mbits[BSZ*SEQ*(SEQ/32)];   // 1 MB bitmask

// ---------------------------------------------------------------------------
__device__ __forceinline__ void mma16(float c[4],
    uint32_t a0, uint32_t a1, uint32_t a2, uint32_t a3, uint32_t b0, uint32_t b1)
{
    asm volatile(
      "mma.sync.aligned.m16n8k16.row.col.f32.f16.f16.f32 "
      "{%0,%1,%2,%3}, {%4,%5,%6,%7}, {%8,%9}, {%0,%1,%2,%3};"
      : "+f"(c[0]), "+f"(c[1]), "+f"(c[2]), "+f"(c[3])
      : "r"(a0), "r"(a1), "r"(a2), "r"(a3), "r"(b0), "r"(b1));
}
__device__ __forceinline__ void ldsm4(uint32_t& r0, uint32_t& r1,
                                      uint32_t& r2, uint32_t& r3, uint32_t a)
{
    asm volatile("ldmatrix.sync.aligned.m8n8.x4.shared.b16 {%0,%1,%2,%3}, [%4];"
                 : "=r"(r0), "=r"(r1), "=r"(r2), "=r"(r3) : "r"(a));
}
__device__ __forceinline__ uint32_t packh2(float a, float b) {
    __half2 h = __floats2half2_rn(a, b);
    return *(uint32_t*)&h;
}
__device__ __forceinline__ uint32_t ex2h2(uint32_t x) {
    uint32_t r; asm("ex2.approx.f16x2 %0, %1;" : "=r"(r) : "r"(x)); return r;
}
__device__ __forceinline__ float msel(float s, uint32_t mw, uint32_t bit) {
    return (mw & bit) ? s : -30.f;
}
__device__ __forceinline__ void cpa16(void* s, const void* g) {
    uint32_t sa = (uint32_t)__cvta_generic_to_shared(s);
    asm volatile("cp.async.cg.shared.global [%0], [%1], 16;" :: "r"(sa), "l"(g));
}
#define CP_COMMIT()  asm volatile("cp.async.commit_group;")
#define CP_WAIT1()   asm volatile("cp.async.wait_group 1;")
#define CP_WAIT0()   asm volatile("cp.async.wait_group 0;")

// ---------------------------------------------------------------------------
// Stage 1: projections + (fused) mask pack + Wo rounding.
// blockIdx.y in {0,1,2}: Q/K/V projection (128 rows/CTA, 256 thr, 8 warps).
// blockIdx.y == 3:       grid-stride mask ballot + Wo fp16 rounding.
// ---------------------------------------------------------------------------
__global__ __launch_bounds__(256) void proj_mma(
    const float* __restrict__ Xq, const float* __restrict__ Xk, const float* __restrict__ Xv,
    const float* __restrict__ Wq, const float* __restrict__ Wk, const float* __restrict__ Wv,
    const int*   __restrict__ mask, const float* __restrict__ Wo)
{
    const int tid = threadIdx.x, lane = tid & 31, w = tid >> 5;

    if (blockIdx.y == 3) {
        // mask: 8.39M words of 32 ints each; 512 CTAs x 8 warps = 4096 warps
        const int gw = blockIdx.x * 8 + w;          // global warp id
        const int nw = 512 * 8;
        const int total_words = BSZ*SEQ*(SEQ/32);   // 262144
        for (int wd = gw; wd < total_words; wd += nw) {
            int idx = wd * 32 + lane;
            uint32_t bits = __ballot_sync(0xffffffffu, mask[idx] != 0);
            if (lane == 0) g_mbits[wd] = bits;
        }
        // Wo rounding: 1M elements over 512*256 threads = 8 each
        const int gt = blockIdx.x * 256 + tid;
        #pragma unroll
        for (int i = 0; i < 8; i++)
            g_Wt[gt + i * (512*256)] = __float2half_rn(Wo[gt + i * (512*256)]);
        return;
    }

    const float* X; const float* W;
    if (blockIdx.y == 0)      { X = Xq; W = Wq; }
    else if (blockIdx.y == 1) { X = Xk; W = Wk; }
    else                      { X = Xv; W = Wv; }

    __shared__ __half Xs[128*SW];
    __shared__ __half Ws[64*SW];
    const size_t rb = (size_t)blockIdx.x * 128;

    float4 xv[8];
    const float4* Xg = (const float4*)(X + rb * 64);
    #pragma unroll
    for (int i = 0; i < 8; i++) xv[i] = Xg[tid + 256*i];
    float4 wv[4];
    const float4* Wg = (const float4*)W;
    #pragma unroll
    for (int i = 0; i < 4; i++) wv[i] = Wg[tid + 256*i];

    #pragma unroll
    for (int i = 0; i < 8; i++) {
        int v = tid + 256*i;
        int r = v >> 4, c4 = v & 15;
        uint32_t* dst = (uint32_t*)Xs + r*SWW + c4*2;
        dst[0] = packh2(xv[i].x, xv[i].y);
        dst[1] = packh2(xv[i].z, xv[i].w);
    }
    #pragma unroll
    for (int i = 0; i < 4; i++) {
        int v = tid + 256*i;
        int r = v >> 4, c4 = v & 15;
        uint32_t* dst = (uint32_t*)Ws + r*SWW + c4*2;
        dst[0] = packh2(wv[i].x, wv[i].y);
        dst[1] = packh2(wv[i].z, wv[i].w);
    }
    __syncthreads();

    const int g = lane >> 2, t = lane & 3;
    const uint32_t lofs = ((lane & 7) + ((lane >> 3) & 1) * 8) * (SW*2) + (lane >> 4) * 16;
    const uint32_t xb = (uint32_t)__cvta_generic_to_shared(Xs) + (16*w)*(SW*2) + lofs;
    const uint32_t wb = (uint32_t)__cvta_generic_to_shared(Ws) + lofs;

    float acc[8][4] = {};
    #pragma unroll
    for (int kc = 0; kc < 4; kc++) {
        uint32_t a0,a1,a2,a3;
        ldsm4(a0,a1,a2,a3, xb + kc*32);
        #pragma unroll
        for (int np = 0; np < 4; np++) {
            uint32_t b0,b1,b2,b3;
            ldsm4(b0,b1,b2,b3, wb + np*16*(SW*2) + kc*32);
            mma16(acc[2*np  ], a0,a1,a2,a3, b0, b2);
            mma16(acc[2*np+1], a0,a1,a2,a3, b1, b3);
        }
    }

    if (blockIdx.y == 0) {
        #pragma unroll
        for (int nt = 0; nt < 8; nt++)
            #pragma unroll
            for (int e = 0; e < 4; e++) acc[nt][e] *= QSCALE;
    }

    if (blockIdx.y < 2) {
        uint32_t* Yw = (uint32_t*)((blockIdx.y == 0) ? g_Qp : g_Kp);
        const size_t rr = rb + 16*w + g;
        #pragma unroll
        for (int nt = 0; nt < 8; nt++) {
            Yw[(rr   ) * 32 + 4*nt + t] = packh2(acc[nt][0], acc[nt][1]);
            Yw[(rr+8 ) * 32 + 4*nt + t] = packh2(acc[nt][2], acc[nt][3]);
        }
    } else {
        const int head = (int)(rb >> 11);
        const int s0 = (int)(rb & 2047) + 16*w + g;
        __half* Vb = g_Vt + (size_t)head * (64*2048);
        #pragma unroll
        for (int nt = 0; nt < 8; nt++) {
            int d0 = 8*nt + 2*t;
            Vb[(size_t)(d0  )*2048 + s0    ] = __float2half_rn(acc[nt][0]);
            Vb[(size_t)(d0+1)*2048 + s0    ] = __float2half_rn(acc[nt][1]);
            Vb[(size_t)(d0  )*2048 + s0 + 8] = __float2half_rn(acc[nt][2]);
            Vb[(size_t)(d0+1)*2048 + s0 + 8] = __float2half_rn(acc[nt][3]);
        }
    }
}

// ---------------------------------------------------------------------------
// Stage 2: fp16 flash attention — R14 structure (volatile mma) with ONE
// isolated change: Q fragments loaded to registers once (removes 8/40 LDSM
// per warp per tile).
// ---------------------------------------------------------------------------
__global__ __launch_bounds__(128) void attn_mma()
{
    extern __shared__ __half sm[];
    __half* Qs   = sm;                        // 128*SW
    __half* Kbuf = sm + 128*SW;               // 2 x 64*SW
    __half* Vbuf = sm + 128*SW + 2*64*SW;     // 2 x 64*SW (Vt layout [d][s])

    const int tid = threadIdx.x, lane = tid & 31, w = tid >> 5;
    const int qb = blockIdx.x * 128, h = blockIdx.y, b = blockIdx.z;
    const int head = b * NH + h;
    const __half* Qp = g_Qp + (size_t)head * SEQ * HD + (size_t)qb * HD;
    const __half* Kp = g_Kp + (size_t)head * SEQ * HD;
    const __half* Vp = g_Vt + (size_t)head * (64*2048);

    for (int v = tid; v < 1024; v += 128) {
        int r = v >> 3, c = (v & 7) * 8;
        cpa16(Qs + r*SW + c, Qp + (size_t)r*64 + c);
    }
    CP_COMMIT();
    for (int v = tid; v < 512; v += 128) {
        int r = v >> 3, c = (v & 7) * 8;
        cpa16(Kbuf + r*SW + c, Kp + (size_t)r*64 + c);
        cpa16(Vbuf + r*SW + c, Vp + (size_t)r*2048 + c);
    }
    CP_COMMIT();

    const int g = lane >> 2, t = lane & 3;
    const int r0 = 32*w + g;
    const uint32_t* mrow[4];
    #pragma unroll
    for (int i = 0; i < 4; i++)
        mrow[i] = g_mbits + ((size_t)b * SEQ + qb + r0 + 8*i) * (SEQ/32);

    const uint32_t lofs = ((lane & 7) + ((lane >> 3) & 1) * 8) * (SW*2) + (lane >> 4) * 16;
    const uint32_t qb0 = (uint32_t)__cvta_generic_to_shared(Qs) + (32*w)*(SW*2) + lofs;
    const uint32_t kb0 = (uint32_t)__cvta_generic_to_shared(Kbuf) + lofs;
    const uint32_t vb0 = (uint32_t)__cvta_generic_to_shared(Vbuf) + lofs;
    const uint32_t bufB = 64*SW*2;

    // Q fragments once (isolated change vs R14)
    CP_WAIT1();
    __syncthreads();
    uint32_t qf[4][8];
    #pragma unroll
    for (int kc = 0; kc < 4; kc++) {
        ldsm4(qf[kc][0], qf[kc][1], qf[kc][2], qf[kc][3], qb0 + kc*32);
        ldsm4(qf[kc][4], qf[kc][5], qf[kc][6], qf[kc][7], qb0 + 16*(SW*2) + kc*32);
    }

    float o0[8][4] = {}, o1[8][4] = {};
    float lac0[4] = {}, lac1[4] = {};

    for (int it = 0; it < 32; ++it) {
        if (it + 1 < 32) {
            const __half* Kn = Kp + (size_t)(it+1) * 64 * 64;
            const __half* Vn = Vp + (size_t)(it+1) * 64;
            __half* kd = Kbuf + ((it+1)&1) * 64*SW;
            __half* vd = Vbuf + ((it+1)&1) * 64*SW;
            for (int v = tid; v < 512; v += 128) {
                int r = v >> 3, c = (v & 7) * 8;
                cpa16(kd + r*SW + c, Kn + (size_t)r*64 + c);
                cpa16(vd + r*SW + c, Vn + (size_t)r*2048 + c);
            }
            CP_COMMIT();
            CP_WAIT1();
        } else {
            CP_WAIT0();
        }
        __syncthreads();
        const uint32_t kcur = kb0 + (it&1) * bufB;
        const uint32_t vcur = vb0 + (it&1) * bufB;

        float s0[8][4] = {}, s1[8][4] = {};
        #pragma unroll
        for (int kc = 0; kc < 4; kc++) {
            #pragma unroll
            for (int np = 0; np < 4; np++) {
                uint32_t kb0r,kb1r,kb2r,kb3r;
                ldsm4(kb0r,kb1r,kb2r,kb3r, kcur + np*16*(SW*2) + kc*32);
                mma16(s0[2*np  ], qf[kc][0],qf[kc][1],qf[kc][2],qf[kc][3], kb0r, kb2r);
                mma16(s0[2*np+1], qf[kc][0],qf[kc][1],qf[kc][2],qf[kc][3], kb1r, kb3r);
                mma16(s1[2*np  ], qf[kc][4],qf[kc][5],qf[kc][6],qf[kc][7], kb0r, kb2r);
                mma16(s1[2*np+1], qf[kc][4],qf[kc][5],qf[kc][6],qf[kc][7], kb1r, kb3r);
            }
        }

        const int wi = it * 2;
        uint32_t mwa[4], mwb[4];
        #pragma unroll
        for (int i = 0; i < 4; i++) { mwa[i] = mrow[i][wi]; mwb[i] = mrow[i][wi+1]; }

        #pragma unroll
        for (int sc = 0; sc < 4; sc++) {
            const uint32_t m0 = (sc < 2) ? mwa[0] : mwb[0];
            const uint32_t m1 = (sc < 2) ? mwa[1] : mwb[1];
            const uint32_t m2 = (sc < 2) ? mwa[2] : mwb[2];
            const uint32_t m3 = (sc < 2) ? mwa[3] : mwb[3];
            const uint32_t cb = (uint32_t)(16*sc + 2*t) & 31u;
            const uint32_t bb0 = 1u << cb, bb1 = bb0 << 1, bb2 = bb0 << 8, bb3 = bb0 << 9;

            uint32_t a0 = ex2h2(packh2(msel(s0[2*sc  ][0],m0,bb0), msel(s0[2*sc  ][1],m0,bb1)));
            uint32_t a1 = ex2h2(packh2(msel(s0[2*sc  ][2],m1,bb0), msel(s0[2*sc  ][3],m1,bb1)));
            uint32_t a2 = ex2h2(packh2(msel(s0[2*sc+1][0],m0,bb2), msel(s0[2*sc+1][1],m0,bb3)));
            uint32_t a3 = ex2h2(packh2(msel(s0[2*sc+1][2],m1,bb2), msel(s0[2*sc+1][3],m1,bb3)));
            uint32_t a4 = ex2h2(packh2(msel(s1[2*sc  ][0],m2,bb0), msel(s1[2*sc  ][1],m2,bb1)));
            uint32_t a5 = ex2h2(packh2(msel(s1[2*sc  ][2],m3,bb0), msel(s1[2*sc  ][3],m3,bb1)));
            uint32_t a6 = ex2h2(packh2(msel(s1[2*sc+1][0],m2,bb2), msel(s1[2*sc+1][1],m2,bb3)));
            uint32_t a7 = ex2h2(packh2(msel(s1[2*sc+1][2],m3,bb2), msel(s1[2*sc+1][3],m3,bb3)));

            mma16(lac0, a0,a1,a2,a3, HONES, HONES);
            mma16(lac1, a4,a5,a6,a7, HONES, HONES);

            #pragma unroll
            for (int dp = 0; dp < 4; dp++) {
                uint32_t vb0r,vb1r,vb2r,vb3r;
                ldsm4(vb0r,vb1r,vb2r,vb3r, vcur + dp*16*(SW*2) + sc*32);
                mma16(o0[2*dp  ], a0,a1,a2,a3, vb0r, vb2r);
                mma16(o0[2*dp+1], a0,a1,a2,a3, vb1r, vb3r);
                mma16(o1[2*dp  ], a4,a5,a6,a7, vb0r, vb2r);
                mma16(o1[2*dp+1], a4,a5,a6,a7, vb1r, vb3r);
            }
        }
        __syncthreads();
    }

    const float il0 = 1.f / lac0[0], il1 = 1.f / lac0[2];
    const float il2 = 1.f / lac1[0], il3 = 1.f / lac1[2];

    uint32_t* Ow = (uint32_t*)(g_O + (size_t)head * SEQ * HD + (size_t)(qb + r0) * 64);
    #pragma unroll
    for (int dt = 0; dt < 8; dt++) {
        int cw = 4*dt + t;
        Ow[          cw] = packh2(o0[dt][0]*il0, o0[dt][1]*il0);
        Ow[ 8*32   + cw] = packh2(o0[dt][2]*il1, o0[dt][3]*il1);
        Ow[16*32   + cw] = packh2(o1[dt][0]*il2, o1[dt][1]*il2);
        Ow[24*32   + cw] = packh2(o1[dt][2]*il3, o1[dt][3]*il3);
    }
}

// ---------------------------------------------------------------------------
// Stage 3: output projection — R14 version (measured 37.4 us)
// ---------------------------------------------------------------------------
__global__ __launch_bounds__(256) void outproj_mma(
    const float* __restrict__ bo, float* __restrict__ out)
{
    extern __shared__ __half sm[];
    __half* Abuf = sm;                  // 2 x 128*SW
    __half* Bbuf = sm + 2*128*SW;       // 2 x 128*SW

    const int tid = threadIdx.x, lane = tid & 31, w = tid >> 5;
    const int g = lane >> 2, t = lane & 3;
    const int wr = w >> 1, wc = w & 1;
    const int nb = blockIdx.x * 128, eb = blockIdx.y * 128;

    for (int v = tid; v < 1024; v += 256) {
        int r = v >> 3, c = (v & 7) * 8;
        cpa16(Abuf + r*SW + c, g_O  + (size_t)(nb + r) * EMB + c);
        cpa16(Bbuf + r*SW + c, g_Wt + (size_t)(eb + r) * EMB + c);
    }
    CP_COMMIT();

    const uint32_t lofs = ((lane & 7) + ((lane >> 3) & 1) * 8) * (SW*2) + (lane >> 4) * 16;
    const uint32_t ab0 = (uint32_t)__cvta_generic_to_shared(Abuf) + (32*wr)*(SW*2) + lofs;
    const uint32_t bb0 = (uint32_t)__cvta_generic_to_shared(Bbuf) + (64*wc)*(SW*2) + lofs;
    const uint32_t bufB = 128*SW*2;

    float acc[2][8][4] = {};

    for (int it = 0; it < 16; ++it) {
        if (it + 1 < 16) {
            const int cb = (it + 1) * 64;
            __half* ad = Abuf + ((it+1)&1) * 128*SW;
            __half* bd = Bbuf + ((it+1)&1) * 128*SW;
            for (int v = tid; v < 1024; v += 256) {
                int r = v >> 3, c = (v & 7) * 8;
                cpa16(ad + r*SW + c, g_O  + (size_t)(nb + r) * EMB + cb + c);
                cpa16(bd + r*SW + c, g_Wt + (size_t)(eb + r) * EMB + cb + c);
            }
            CP_COMMIT();
            CP_WAIT1();
        } else {
            CP_WAIT0();
        }
        __syncthreads();
        const uint32_t acur = ab0 + (it&1) * bufB;
        const uint32_t bcur = bb0 + (it&1) * bufB;

        #pragma unroll
        for (int kc = 0; kc < 4; kc++) {
            uint32_t af[2][4];
            #pragma unroll
            for (int m = 0; m < 2; m++)
                ldsm4(af[m][0], af[m][1], af[m][2], af[m][3],
                      acur + m*16*(SW*2) + kc*32);
            #pragma unroll
            for (int np = 0; np < 4; np++) {
                uint32_t b0r,b1r,b2r,b3r;
                ldsm4(b0r,b1r,b2r,b3r, bcur + np*16*(SW*2) + kc*32);
                #pragma unroll
                for (int m = 0; m < 2; m++) {
                    mma16(acc[m][2*np  ], af[m][0],af[m][1],af[m][2],af[m][3], b0r, b2r);
                    mma16(acc[m][2*np+1], af[m][0],af[m][1],af[m][2],af[m][3], b1r, b3r);
                }
            }
        }
        __syncthreads();
    }

    #pragma unroll
    for (int m = 0; m < 2; m++) {
        const int row0 = nb + 32*wr + 16*m + g;
        #pragma unroll
        for (int nt = 0; nt < 8; nt++) {
            int c0 = eb + 64*wc + 8*nt + 2*t;
            float b0 = bo[c0], b1 = bo[c0+1];
            *(float2*)(out + (size_t)row0     * EMB + c0) =
                make_float2(acc[m][nt][0] + b0, acc[m][nt][1] + b1);
            *(float2*)(out + (size_t)(row0+8) * EMB + c0) =
                make_float2(acc[m][nt][2] + b0, acc[m][nt][3] + b1);
        }
    }
}

// ---------------------------------------------------------------------------
extern "C" void kernel_launch(void* const* d_in, const int* in_sizes, int n_in,
                              void* d_out, int out_size)
{
    const float* query = (const float*)d_in[0];
    const float* key   = (const float*)d_in[1];
    const float* value = (const float*)d_in[2];
    const int*   mask  = (const int*)  d_in[3];
    const float* Wq    = (const float*)d_in[4];
    const float* Wk    = (const float*)d_in[5];
    const float* Wv    = (const float*)d_in[6];
    const float* Wo    = (const float*)d_in[7];
    const float* bo    = (const float*)d_in[8];
    float* out = (float*)d_out;

    dim3 pg(NROWS/128, 4, 1);   // y=0..2 proj, y=3 mask/Wo prep (fused)
    proj_mma<<<pg, 256>>>(query, key, value, Wq, Wk, Wv, mask, Wo);

    const int attn_smem = (128*SW + 4*64*SW) * 2;   // 55,296 B
    cudaFuncSetAttribute(attn_mma, cudaFuncAttributeMaxDynamicSharedMemorySize, attn_smem);
    dim3 ag(SEQ/128, NH, BSZ);
    attn_mma<<<ag, 128, attn_smem>>>();

    const int op_smem = 4*128*SW*2;                 // 73,728 B
    cudaFuncSetAttribute(outproj_mma, cudaFuncAttributeMaxDynamicSharedMemorySize, op_smem);
    dim3 og(NTOK/128, EMB/128, 1);
    outproj_mma<<<og, 256, op_smem>>>(bo, out);
}

// round 17
// speedup vs baseline: 1.0547x; 1.0423x over previous
#include <cuda_runtime.h>
#include <cuda_fp16.h>
#include <cstdint>

#define BSZ  2
#define SEQ  2048
#define EMB  1024
#define NH   16
#define HD   64
#define NROWS (BSZ*NH*SEQ)
#define NTOK  (BSZ*SEQ)
#define SW   72
#define SWW  36
#define QSCALE 0.045084220027780106f   // (1/32) * log2(e)
#define HONES 0x3C003C00u              // half2(1.0, 1.0)

__device__ __half g_Qp[NROWS*HD];      // [head][s][d] fp16, pre-scaled
__device__ __half g_Kp[NROWS*HD];      // [head][s][d] fp16
__device__ __half g_Vt[NROWS*HD];      // [head][d][s] fp16 (transposed)
__device__ __half g_O [NROWS*HD];      // flat == [NTOK][EMB] fp16
__device__ __half g_Wt[EMB*EMB];       // Wo fp16
__device__ uint32_t g_mbits[BSZ*SEQ*(SEQ/32)];   // 1 MB bitmask

// ---------------------------------------------------------------------------
__device__ __forceinline__ void mma16(float c[4],
    uint32_t a0, uint32_t a1, uint32_t a2, uint32_t a3, uint32_t b0, uint32_t b1)
{
    asm volatile(
      "mma.sync.aligned.m16n8k16.row.col.f32.f16.f16.f32 "
      "{%0,%1,%2,%3}, {%4,%5,%6,%7}, {%8,%9}, {%0,%1,%2,%3};"
      : "+f"(c[0]), "+f"(c[1]), "+f"(c[2]), "+f"(c[3])
      : "r"(a0), "r"(a1), "r"(a2), "r"(a3), "r"(b0), "r"(b1));
}
__device__ __forceinline__ void ldsm4(uint32_t& r0, uint32_t& r1,
                                      uint32_t& r2, uint32_t& r3, uint32_t a)
{
    asm volatile("ldmatrix.sync.aligned.m8n8.x4.shared.b16 {%0,%1,%2,%3}, [%4];"
                 : "=r"(r0), "=r"(r1), "=r"(r2), "=r"(r3) : "r"(a));
}
__device__ __forceinline__ uint32_t packh2(float a, float b) {
    __half2 h = __floats2half2_rn(a, b);
    return *(uint32_t*)&h;
}
__device__ __forceinline__ uint32_t ex2h2(uint32_t x) {
    uint32_t r; asm("ex2.approx.f16x2 %0, %1;" : "=r"(r) : "r"(x)); return r;
}
__device__ __forceinline__ float msel(float s, uint32_t mw, uint32_t bit) {
    return (mw & bit) ? s : -30.f;
}
__device__ __forceinline__ void cpa16(void* s, const void* g) {
    uint32_t sa = (uint32_t)__cvta_generic_to_shared(s);
    asm volatile("cp.async.cg.shared.global [%0], [%1], 16;" :: "r"(sa), "l"(g));
}
#define CP_COMMIT()  asm volatile("cp.async.commit_group;")
#define CP_WAIT1()   asm volatile("cp.async.wait_group 1;")
#define CP_WAIT0()   asm volatile("cp.async.wait_group 0;")

// ---------------------------------------------------------------------------
// Stage 1: projections + fused mask pack + Wo rounding (R16 version, 40 us)
// ---------------------------------------------------------------------------
__global__ __launch_bounds__(256) void proj_mma(
    const float* __restrict__ Xq, const float* __restrict__ Xk, const float* __restrict__ Xv,
    const float* __restrict__ Wq, const float* __restrict__ Wk, const float* __restrict__ Wv,
    const int*   __restrict__ mask, const float* __restrict__ Wo)
{
    const int tid = threadIdx.x, lane = tid & 31, w = tid >> 5;

    if (blockIdx.y == 3) {
        const int gw = blockIdx.x * 8 + w;
        const int nw = 512 * 8;
        const int total_words = BSZ*SEQ*(SEQ/32);
        for (int wd = gw; wd < total_words; wd += nw) {
            int idx = wd * 32 + lane;
            uint32_t bits = __ballot_sync(0xffffffffu, mask[idx] != 0);
            if (lane == 0) g_mbits[wd] = bits;
        }
        const int gt = blockIdx.x * 256 + tid;
        #pragma unroll
        for (int i = 0; i < 8; i++)
            g_Wt[gt + i * (512*256)] = __float2half_rn(Wo[gt + i * (512*256)]);
        return;
    }

    const float* X; const float* W;
    if (blockIdx.y == 0)      { X = Xq; W = Wq; }
    else if (blockIdx.y == 1) { X = Xk; W = Wk; }
    else                      { X = Xv; W = Wv; }

    __shared__ __half Xs[128*SW];
    __shared__ __half Ws[64*SW];
    const size_t rb = (size_t)blockIdx.x * 128;

    float4 xv[8];
    const float4* Xg = (const float4*)(X + rb * 64);
    #pragma unroll
    for (int i = 0; i < 8; i++) xv[i] = Xg[tid + 256*i];
    float4 wv[4];
    const float4* Wg = (const float4*)W;
    #pragma unroll
    for (int i = 0; i < 4; i++) wv[i] = Wg[tid + 256*i];

    #pragma unroll
    for (int i = 0; i < 8; i++) {
        int v = tid + 256*i;
        int r = v >> 4, c4 = v & 15;
        uint32_t* dst = (uint32_t*)Xs + r*SWW + c4*2;
        dst[0] = packh2(xv[i].x, xv[i].y);
        dst[1] = packh2(xv[i].z, xv[i].w);
    }
    #pragma unroll
    for (int i = 0; i < 4; i++) {
        int v = tid + 256*i;
        int r = v >> 4, c4 = v & 15;
        uint32_t* dst = (uint32_t*)Ws + r*SWW + c4*2;
        dst[0] = packh2(wv[i].x, wv[i].y);
        dst[1] = packh2(wv[i].z, wv[i].w);
    }
    __syncthreads();

    const int g = lane >> 2, t = lane & 3;
    const uint32_t lofs = ((lane & 7) + ((lane >> 3) & 1) * 8) * (SW*2) + (lane >> 4) * 16;
    const uint32_t xb = (uint32_t)__cvta_generic_to_shared(Xs) + (16*w)*(SW*2) + lofs;
    const uint32_t wb = (uint32_t)__cvta_generic_to_shared(Ws) + lofs;

    float acc[8][4] = {};
    #pragma unroll
    for (int kc = 0; kc < 4; kc++) {
        uint32_t a0,a1,a2,a3;
        ldsm4(a0,a1,a2,a3, xb + kc*32);
        #pragma unroll
        for (int np = 0; np < 4; np++) {
            uint32_t b0,b1,b2,b3;
            ldsm4(b0,b1,b2,b3, wb + np*16*(SW*2) + kc*32);
            mma16(acc[2*np  ], a0,a1,a2,a3, b0, b2);
            mma16(acc[2*np+1], a0,a1,a2,a3, b1, b3);
        }
    }

    if (blockIdx.y == 0) {
        #pragma unroll
        for (int nt = 0; nt < 8; nt++)
            #pragma unroll
            for (int e = 0; e < 4; e++) acc[nt][e] *= QSCALE;
    }

    if (blockIdx.y < 2) {
        uint32_t* Yw = (uint32_t*)((blockIdx.y == 0) ? g_Qp : g_Kp);
        const size_t rr = rb + 16*w + g;
        #pragma unroll
        for (int nt = 0; nt < 8; nt++) {
            Yw[(rr   ) * 32 + 4*nt + t] = packh2(acc[nt][0], acc[nt][1]);
            Yw[(rr+8 ) * 32 + 4*nt + t] = packh2(acc[nt][2], acc[nt][3]);
        }
    } else {
        const int head = (int)(rb >> 11);
        const int s0 = (int)(rb & 2047) + 16*w + g;
        __half* Vb = g_Vt + (size_t)head * (64*2048);
        #pragma unroll
        for (int nt = 0; nt < 8; nt++) {
            int d0 = 8*nt + 2*t;
            Vb[(size_t)(d0  )*2048 + s0    ] = __float2half_rn(acc[nt][0]);
            Vb[(size_t)(d0+1)*2048 + s0    ] = __float2half_rn(acc[nt][1]);
            Vb[(size_t)(d0  )*2048 + s0 + 8] = __float2half_rn(acc[nt][2]);
            Vb[(size_t)(d0+1)*2048 + s0 + 8] = __float2half_rn(acc[nt][3]);
        }
    }
}

// ---------------------------------------------------------------------------
// Stage 2: fp16 flash attention — R14 math, fragment loads software-pipelined:
// S phase: Q+K frags double-buffered per kc chunk (prefetch before mmas).
// PV phase: V frags rotated one dp ahead.
// ---------------------------------------------------------------------------
__global__ __launch_bounds__(128) void attn_mma()
{
    extern __shared__ __half sm[];
    __half* Qs   = sm;                        // 128*SW
    __half* Kbuf = sm + 128*SW;               // 2 x 64*SW
    __half* Vbuf = sm + 128*SW + 2*64*SW;     // 2 x 64*SW (Vt layout [d][s])

    const int tid = threadIdx.x, lane = tid & 31, w = tid >> 5;
    const int qb = blockIdx.x * 128, h = blockIdx.y, b = blockIdx.z;
    const int head = b * NH + h;
    const __half* Qp = g_Qp + (size_t)head * SEQ * HD + (size_t)qb * HD;
    const __half* Kp = g_Kp + (size_t)head * SEQ * HD;
    const __half* Vp = g_Vt + (size_t)head * (64*2048);

    for (int v = tid; v < 1024; v += 128) {
        int r = v >> 3, c = (v & 7) * 8;
        cpa16(Qs + r*SW + c, Qp + (size_t)r*64 + c);
    }
    for (int v = tid; v < 512; v += 128) {
        int r = v >> 3, c = (v & 7) * 8;
        cpa16(Kbuf + r*SW + c, Kp + (size_t)r*64 + c);
        cpa16(Vbuf + r*SW + c, Vp + (size_t)r*2048 + c);
    }
    CP_COMMIT();

    const int g = lane >> 2, t = lane & 3;
    const int r0 = 32*w + g;
    const uint32_t* mrow[4];
    #pragma unroll
    for (int i = 0; i < 4; i++)
        mrow[i] = g_mbits + ((size_t)b * SEQ + qb + r0 + 8*i) * (SEQ/32);

    const uint32_t lofs = ((lane & 7) + ((lane >> 3) & 1) * 8) * (SW*2) + (lane >> 4) * 16;
    const uint32_t qb0 = (uint32_t)__cvta_generic_to_shared(Qs) + (32*w)*(SW*2) + lofs;
    const uint32_t kb0 = (uint32_t)__cvta_generic_to_shared(Kbuf) + lofs;
    const uint32_t vb0 = (uint32_t)__cvta_generic_to_shared(Vbuf) + lofs;
    const uint32_t bufB = 64*SW*2;

    float o0[8][4] = {}, o1[8][4] = {};
    float lac0[4] = {}, lac1[4] = {};

    for (int it = 0; it < 32; ++it) {
        if (it + 1 < 32) {
            const __half* Kn = Kp + (size_t)(it+1) * 64 * 64;
            const __half* Vn = Vp + (size_t)(it+1) * 64;
            __half* kd = Kbuf + ((it+1)&1) * 64*SW;
            __half* vd = Vbuf + ((it+1)&1) * 64*SW;
            for (int v = tid; v < 512; v += 128) {
                int r = v >> 3, c = (v & 7) * 8;
                cpa16(kd + r*SW + c, Kn + (size_t)r*64 + c);
                cpa16(vd + r*SW + c, Vn + (size_t)r*2048 + c);
            }
            CP_COMMIT();
            CP_WAIT1();
        } else {
            CP_WAIT0();
        }
        __syncthreads();
        const uint32_t kcur = kb0 + (it&1) * bufB;
        const uint32_t vcur = vb0 + (it&1) * bufB;

        // S = Q @ K^T — Q/K frags double-buffered per kc chunk
        float s0[8][4] = {}, s1[8][4] = {};
        {
            uint32_t qf[2][8], kf[2][16];
            ldsm4(qf[0][0],qf[0][1],qf[0][2],qf[0][3], qb0);
            ldsm4(qf[0][4],qf[0][5],qf[0][6],qf[0][7], qb0 + 16*(SW*2));
            #pragma unroll
            for (int np = 0; np < 4; np++)
                ldsm4(kf[0][4*np],kf[0][4*np+1],kf[0][4*np+2],kf[0][4*np+3],
                      kcur + np*16*(SW*2));
            #pragma unroll
            for (int kc = 0; kc < 4; kc++) {
                const int cur = kc & 1, nxt = cur ^ 1;
                if (kc < 3) {
                    ldsm4(qf[nxt][0],qf[nxt][1],qf[nxt][2],qf[nxt][3],
                          qb0 + (kc+1)*32);
                    ldsm4(qf[nxt][4],qf[nxt][5],qf[nxt][6],qf[nxt][7],
                          qb0 + 16*(SW*2) + (kc+1)*32);
                    #pragma unroll
                    for (int np = 0; np < 4; np++)
                        ldsm4(kf[nxt][4*np],kf[nxt][4*np+1],kf[nxt][4*np+2],kf[nxt][4*np+3],
                              kcur + np*16*(SW*2) + (kc+1)*32);
                }
                #pragma unroll
                for (int np = 0; np < 4; np++) {
                    mma16(s0[2*np  ], qf[cur][0],qf[cur][1],qf[cur][2],qf[cur][3],
                          kf[cur][4*np], kf[cur][4*np+2]);
                    mma16(s0[2*np+1], qf[cur][0],qf[cur][1],qf[cur][2],qf[cur][3],
                          kf[cur][4*np+1], kf[cur][4*np+3]);
                    mma16(s1[2*np  ], qf[cur][4],qf[cur][5],qf[cur][6],qf[cur][7],
                          kf[cur][4*np], kf[cur][4*np+2]);
                    mma16(s1[2*np+1], qf[cur][4],qf[cur][5],qf[cur][6],qf[cur][7],
                          kf[cur][4*np+1], kf[cur][4*np+3]);
                }
            }
        }

        const int wi = it * 2;
        uint32_t mwa[4], mwb[4];
        #pragma unroll
        for (int i = 0; i < 4; i++) { mwa[i] = mrow[i][wi]; mwb[i] = mrow[i][wi+1]; }

        #pragma unroll
        for (int sc = 0; sc < 4; sc++) {
            const uint32_t m0 = (sc < 2) ? mwa[0] : mwb[0];
            const uint32_t m1 = (sc < 2) ? mwa[1] : mwb[1];
            const uint32_t m2 = (sc < 2) ? mwa[2] : mwb[2];
            const uint32_t m3 = (sc < 2) ? mwa[3] : mwb[3];
            const uint32_t cb = (uint32_t)(16*sc + 2*t) & 31u;
            const uint32_t bb0 = 1u << cb, bb1 = bb0 << 1, bb2 = bb0 << 8, bb3 = bb0 << 9;

            uint32_t a0 = ex2h2(packh2(msel(s0[2*sc  ][0],m0,bb0), msel(s0[2*sc  ][1],m0,bb1)));
            uint32_t a1 = ex2h2(packh2(msel(s0[2*sc  ][2],m1,bb0), msel(s0[2*sc  ][3],m1,bb1)));
            uint32_t a2 = ex2h2(packh2(msel(s0[2*sc+1][0],m0,bb2), msel(s0[2*sc+1][1],m0,bb3)));
            uint32_t a3 = ex2h2(packh2(msel(s0[2*sc+1][2],m1,bb2), msel(s0[2*sc+1][3],m1,bb3)));
            uint32_t a4 = ex2h2(packh2(msel(s1[2*sc  ][0],m2,bb0), msel(s1[2*sc  ][1],m2,bb1)));
            uint32_t a5 = ex2h2(packh2(msel(s1[2*sc  ][2],m3,bb0), msel(s1[2*sc  ][3],m3,bb1)));
            uint32_t a6 = ex2h2(packh2(msel(s1[2*sc+1][0],m2,bb2), msel(s1[2*sc+1][1],m2,bb3)));
            uint32_t a7 = ex2h2(packh2(msel(s1[2*sc+1][2],m3,bb2), msel(s1[2*sc+1][3],m3,bb3)));

            mma16(lac0, a0,a1,a2,a3, HONES, HONES);
            mma16(lac1, a4,a5,a6,a7, HONES, HONES);

            // V frags rotated one dp ahead
            uint32_t vc0,vc1,vc2,vc3, vn0,vn1,vn2,vn3;
            ldsm4(vc0,vc1,vc2,vc3, vcur + sc*32);
            #pragma unroll
            for (int dp = 0; dp < 4; dp++) {
                if (dp < 3)
                    ldsm4(vn0,vn1,vn2,vn3, vcur + (dp+1)*16*(SW*2) + sc*32);
                mma16(o0[2*dp  ], a0,a1,a2,a3, vc0, vc2);
                mma16(o0[2*dp+1], a0,a1,a2,a3, vc1, vc3);
                mma16(o1[2*dp  ], a4,a5,a6,a7, vc0, vc2);
                mma16(o1[2*dp+1], a4,a5,a6,a7, vc1, vc3);
                vc0 = vn0; vc1 = vn1; vc2 = vn2; vc3 = vn3;
            }
        }
        __syncthreads();
    }

    const float il0 = 1.f / lac0[0], il1 = 1.f / lac0[2];
    const float il2 = 1.f / lac1[0], il3 = 1.f / lac1[2];

    uint32_t* Ow = (uint32_t*)(g_O + (size_t)head * SEQ * HD + (size_t)(qb + r0) * 64);
    #pragma unroll
    for (int dt = 0; dt < 8; dt++) {
        int cw = 4*dt + t;
        Ow[          cw] = packh2(o0[dt][0]*il0, o0[dt][1]*il0);
        Ow[ 8*32   + cw] = packh2(o0[dt][2]*il1, o0[dt][3]*il1);
        Ow[16*32   + cw] = packh2(o1[dt][0]*il2, o1[dt][1]*il2);
        Ow[24*32   + cw] = packh2(o1[dt][2]*il3, o1[dt][3]*il3);
    }
}

// ---------------------------------------------------------------------------
// Stage 3: output projection — R14 tiling + double-buffered fragments per kc.
// ---------------------------------------------------------------------------
__global__ __launch_bounds__(256) void outproj_mma(
    const float* __restrict__ bo, float* __restrict__ out)
{
    extern __shared__ __half sm[];
    __half* Abuf = sm;                  // 2 x 128*SW
    __half* Bbuf = sm + 2*128*SW;       // 2 x 128*SW

    const int tid = threadIdx.x, lane = tid & 31, w = tid >> 5;
    const int g = lane >> 2, t = lane & 3;
    const int wr = w >> 1, wc = w & 1;
    const int nb = blockIdx.x * 128, eb = blockIdx.y * 128;

    for (int v = tid; v < 1024; v += 256) {
        int r = v >> 3, c = (v & 7) * 8;
        cpa16(Abuf + r*SW + c, g_O  + (size_t)(nb + r) * EMB + c);
        cpa16(Bbuf + r*SW + c, g_Wt + (size_t)(eb + r) * EMB + c);
    }
    CP_COMMIT();

    const uint32_t lofs = ((lane & 7) + ((lane >> 3) & 1) * 8) * (SW*2) + (lane >> 4) * 16;
    const uint32_t ab0 = (uint32_t)__cvta_generic_to_shared(Abuf) + (32*wr)*(SW*2) + lofs;
    const uint32_t bb0 = (uint32_t)__cvta_generic_to_shared(Bbuf) + (64*wc)*(SW*2) + lofs;
    const uint32_t bufB = 128*SW*2;

    float acc[2][8][4] = {};

    for (int it = 0; it < 16; ++it) {
        if (it + 1 < 16) {
            const int cb = (it + 1) * 64;
            __half* ad = Abuf + ((it+1)&1) * 128*SW;
            __half* bd = Bbuf + ((it+1)&1) * 128*SW;
            for (int v = tid; v < 1024; v += 256) {
                int r = v >> 3, c = (v & 7) * 8;
                cpa16(ad + r*SW + c, g_O  + (size_t)(nb + r) * EMB + cb + c);
                cpa16(bd + r*SW + c, g_Wt + (size_t)(eb + r) * EMB + cb + c);
            }
            CP_COMMIT();
            CP_WAIT1();
        } else {
            CP_WAIT0();
        }
        __syncthreads();
        const uint32_t acur = ab0 + (it&1) * bufB;
        const uint32_t bcur = bb0 + (it&1) * bufB;

        uint32_t af[2][8], bf[2][16];
        #pragma unroll
        for (int m = 0; m < 2; m++)
            ldsm4(af[0][4*m],af[0][4*m+1],af[0][4*m+2],af[0][4*m+3],
                  acur + m*16*(SW*2));
        #pragma unroll
        for (int np = 0; np < 4; np++)
            ldsm4(bf[0][4*np],bf[0][4*np+1],bf[0][4*np+2],bf[0][4*np+3],
                  bcur + np*16*(SW*2));

        #pragma unroll
        for (int kc = 0; kc < 4; kc++) {
            const int cur = kc & 1, nxt = cur ^ 1;
            if (kc < 3) {
                #pragma unroll
                for (int m = 0; m < 2; m++)
                    ldsm4(af[nxt][4*m],af[nxt][4*m+1],af[nxt][4*m+2],af[nxt][4*m+3],
                          acur + m*16*(SW*2) + (kc+1)*32);
                #pragma unroll
                for (int np = 0; np < 4; np++)
                    ldsm4(bf[nxt][4*np],bf[nxt][4*np+1],bf[nxt][4*np+2],bf[nxt][4*np+3],
                          bcur + np*16*(SW*2) + (kc+1)*32);
            }
            #pragma unroll
            for (int np = 0; np < 4; np++)
                #pragma unroll
                for (int m = 0; m < 2; m++) {
                    mma16(acc[m][2*np  ], af[cur][4*m],af[cur][4*m+1],af[cur][4*m+2],af[cur][4*m+3],
                          bf[cur][4*np], bf[cur][4*np+2]);
                    mma16(acc[m][2*np+1], af[cur][4*m],af[cur][4*m+1],af[cur][4*m+2],af[cur][4*m+3],
                          bf[cur][4*np+1], bf[cur][4*np+3]);
                }
        }
        __syncthreads();
    }

    #pragma unroll
    for (int m = 0; m < 2; m++) {
        const int row0 = nb + 32*wr + 16*m + g;
        #pragma unroll
        for (int nt = 0; nt < 8; nt++) {
            int c0 = eb + 64*wc + 8*nt + 2*t;
            float b0 = bo[c0], b1 = bo[c0+1];
            *(float2*)(out + (size_t)row0     * EMB + c0) =
                make_float2(acc[m][nt][0] + b0, acc[m][nt][1] + b1);
            *(float2*)(out + (size_t)(row0+8) * EMB + c0) =
                make_float2(acc[m][nt][2] + b0, acc[m][nt][3] + b1);
        }
    }
}

// ---------------------------------------------------------------------------
extern "C" void kernel_launch(void* const* d_in, const int* in_sizes, int n_in,
                              void* d_out, int out_size)
{
    const float* query = (const float*)d_in[0];
    const float* key   = (const float*)d_in[1];
    const float* value = (const float*)d_in[2];
    const int*   mask  = (const int*)  d_in[3];
    const float* Wq    = (const float*)d_in[4];
    const float* Wk    = (const float*)d_in[5];
    const float* Wv    = (const float*)d_in[6];
    const float* Wo    = (const float*)d_in[7];
    const float* bo    = (const float*)d_in[8];
    float* out = (float*)d_out;

    dim3 pg(NROWS/128, 4, 1);   // y=0..2 proj, y=3 mask/Wo prep (fused)
    proj_mma<<<pg, 256>>>(query, key, value, Wq, Wk, Wv, mask, Wo);

    const int attn_smem = (128*SW + 4*64*SW) * 2;   // 55,296 B
    cudaFuncSetAttribute(attn_mma, cudaFuncAttributeMaxDynamicSharedMemorySize, attn_smem);
    dim3 ag(SEQ/128, NH, BSZ);
    attn_mma<<<ag, 128, attn_smem>>>();

    const int op_smem = 4*128*SW*2;                 // 73,728 B
    cudaFuncSetAttribute(outproj_mma, cudaFuncAttributeMaxDynamicSharedMemorySize, op_smem);
    dim3 og(NTOK/128, EMB/128, 1);
    outproj_mma<<<og, 256, op_smem>>>(bo, out);
}